// round 11
// baseline (speedup 1.0000x reference)
#include <cuda_runtime.h>
#include <cuda_fp16.h>
#include <stdint.h>

#define B_ 2
#define N_ 512
#define IN_DIM 512
#define EMB 64
#define HID 128
#define NPOS 1025

// ---------------- device scratch (no cudaMalloc allowed) ----------------
__device__ float g_sl[B_ * N_ * EMB];
__device__ float g_sr[B_ * N_ * EMB];
__device__ float g_P[NPOS * HID];
__device__ unsigned short g_W1Th[HID * EMB];   // fp16(W1_top^T) [j][d]
__device__ unsigned short g_W2Th[EMB * HID];   // fp16(W2^T) [o][j]

// ---------------- helpers ----------------
__device__ __forceinline__ uint32_t smem_u32_of(const void* p) {
    uint32_t a;
    asm("{ .reg .u64 t; cvta.to.shared.u64 t, %1; cvt.u32.u64 %0, t; }"
        : "=r"(a) : "l"(p));
    return a;
}
// fp16 hi/lo split of a float pair -> (hi_half2, lo_half2)
__device__ __forceinline__ uint2 split2h(float e0, float e1) {
    __half2 h = __floats2half2_rn(e0, e1);
    float f0 = __half2float(__low2half(h));
    float f1 = __half2float(__high2half(h));
    __half2 lo = __floats2half2_rn(e0 - f0, e1 - f1);
    return make_uint2(*reinterpret_cast<uint32_t*>(&h),
                      *reinterpret_cast<uint32_t*>(&lo));
}
__device__ __forceinline__ void mma16816(float* c, const uint32_t* a,
                                         uint32_t b0, uint32_t b1) {
    asm volatile(
        "mma.sync.aligned.m16n8k16.row.col.f32.f16.f16.f32 "
        "{%0,%1,%2,%3}, {%4,%5,%6,%7}, {%8,%9}, {%0,%1,%2,%3};"
        : "+f"(c[0]), "+f"(c[1]), "+f"(c[2]), "+f"(c[3])
        : "r"(a[0]), "r"(a[1]), "r"(a[2]), "r"(a[3]), "r"(b0), "r"(b1));
}
__device__ __forceinline__ void ldsm4(uint32_t* r, uint32_t addr) {
    asm volatile("ldmatrix.sync.aligned.m8n8.x4.shared.b16 {%0,%1,%2,%3}, [%4];"
                 : "=r"(r[0]), "=r"(r[1]), "=r"(r[2]), "=r"(r[3]) : "r"(addr));
}

// ---------------- kernel 1: projections ----------------
__global__ void proj2_kernel(const float* __restrict__ s,
                             const float* __restrict__ Wl, const float* __restrict__ bl,
                             const float* __restrict__ Wr, const float* __restrict__ br) {
    extern __shared__ float psm[];
    float* SsT = psm;              // [512][20]
    float* Wc  = psm + 512 * 20;   // [64][128]

    const int t = threadIdx.x;
    const int r0 = blockIdx.x * 16;

    for (int i = t; i < 16 * IN_DIM; i += 256) {
        int row = i >> 9, k = i & 511;
        SsT[k * 20 + row] = s[(size_t)(r0 + row) * IN_DIM + k];
    }

    const int col = t & 127, rg = t >> 7;
    float acc[8];
    const float bias = (col < 64) ? bl[col] : br[col - 64];
#pragma unroll
    for (int r = 0; r < 8; r++) acc[r] = bias;
    __syncthreads();

    for (int kt = 0; kt < 8; kt++) {
        for (int i = t; i < 64 * 128; i += 256) {
            int k = i >> 7, c = i & 127;
            Wc[i] = (c < 64) ? Wl[(size_t)(kt * 64 + k) * 64 + c]
                             : Wr[(size_t)(kt * 64 + k) * 64 + (c - 64)];
        }
        __syncthreads();
#pragma unroll 4
        for (int k = 0; k < 64; k++) {
            float w = Wc[k * 128 + col];
            const float* sp = &SsT[(kt * 64 + k) * 20 + rg * 8];
            float4 a0 = *(const float4*)sp;
            float4 a1 = *(const float4*)(sp + 4);
            acc[0] += a0.x * w; acc[1] += a0.y * w; acc[2] += a0.z * w; acc[3] += a0.w * w;
            acc[4] += a1.x * w; acc[5] += a1.y * w; acc[6] += a1.z * w; acc[7] += a1.w * w;
        }
        __syncthreads();
    }
#pragma unroll
    for (int r = 0; r < 8; r++) {
        int row = r0 + rg * 8 + r;
        if (col < 64) g_sl[(size_t)row * 64 + col] = acc[r];
        else          g_sr[(size_t)row * 64 + (col - 64)] = acc[r];
    }
}

// ---------------- kernel 2: weight transposes -> fp16 ----------------
__global__ void prep_kernel(const float* __restrict__ W1, const float* __restrict__ W2) {
    int i = blockIdx.x * 256 + threadIdx.x;
    if (i < HID * EMB) {
        {
            int j = i >> 6, d = i & 63;
            g_W1Th[i] = __half_as_ushort(__float2half_rn(W1[d * HID + j]));
        }
        {
            int o = i & 63, jj = i >> 6;
            g_W2Th[o * HID + jj] = __half_as_ushort(__float2half_rn(W2[jj * EMB + o]));
        }
    }
}

// ---------------- kernel 3: positional table ----------------
__global__ void pos_kernel(const float* __restrict__ emb,
                           const float* __restrict__ W1,
                           const float* __restrict__ b1) {
    __shared__ float erow[EMB];
    const int dist = blockIdx.x;
    const int h = threadIdx.x;
    if (h < EMB) erow[h] = emb[dist * EMB + h];
    __syncthreads();
    float acc = b1[h];
#pragma unroll
    for (int d = 0; d < EMB; d++)
        acc = fmaf(erow[d], W1[(EMB + d) * HID + h], acc);
    g_P[dist * HID + h] = acc;
}

// ---------------- main kernel: 32 m-rows/warp, sequential j-halves, 1 CTA ----------------
// smem: sl 256B | b2 256B | W1 [128 j][72 fp16] 144B-stride | W2 [64 o][136] 272B-stride
#define OFF_SL   0
#define OFF_B2S  256
#define OFF_W1   512
#define OFF_W2   (OFF_W1 + 18432)
#define SMEM_MAIN (OFF_W2 + 17408)   // 36352 bytes

__global__ __launch_bounds__(256, 1)
void pair_mma_kernel(const float* __restrict__ b2, float* __restrict__ out) {
    extern __shared__ char sm[];
    const uint32_t smb = smem_u32_of(sm);
    const int tid = threadIdx.x;
    const int w = tid >> 5, l = tid & 31;
    const int n = blockIdx.x, b = blockIdx.y;

    float* sl = (float*)(sm + OFF_SL);
    float* b2s = (float*)(sm + OFF_B2S);
    if (tid < 64) {
        sl[tid] = g_sl[((size_t)b * N_ + n) * EMB + tid];
        b2s[tid] = b2[tid];
    }

    for (int i = tid; i < 2048; i += 256) {
        int j = i >> 4, d8 = (i & 15) * 8;
        *(uint2*)(sm + OFF_W1 + j * 144 + d8) = ((const uint2*)g_W1Th)[i];
    }
    for (int i = tid; i < 2048; i += 256) {
        int o = i >> 5, j8 = (i & 31) * 8;
        *(uint2*)(sm + OFF_W2 + o * 272 + j8) = ((const uint2*)g_W2Th)[i];
    }

    // ---- per-thread ldmatrix base addresses for B operands (x4 forms) ----
    const uint32_t preB1 = smb + OFF_W1 +
        ((l & 7) + ((l >> 4) << 3)) * 144 + ((l >> 3) & 1) * 16;
    const uint32_t preB2 = smb + OFF_W2 +
        ((l & 7) + ((l >> 4) << 3)) * 272 + ((l >> 3) & 1) * 16;

    const int fc0 = (l & 3) * 2;
    const int lr = l >> 2;

    __syncthreads();   // smem read-only below: the main loop has NO barriers

    for (int p = 0; p < 2; p++) {
        const int mw = p * 256 + 32 * w;        // warp's 32-row base

        // ---- build GEMM1 A fragments in registers: 2 m-frags x 4 k-chunks, hi/lo ----
        uint32_t ah[2][4][4], al[2][4][4];
#pragma unroll
        for (int f = 0; f < 2; f++) {
            const float* sr0 = g_sr + ((size_t)(b * N_ + mw + 16 * f + lr)) * EMB;
            const float* sr8 = sr0 + 8 * EMB;
#pragma unroll
            for (int t = 0; t < 4; t++) {
                const int c = fc0 + 16 * t;
                float2 v00 = *(const float2*)(sr0 + c);
                float2 v01 = *(const float2*)(sr0 + c + 8);
                float2 v10 = *(const float2*)(sr8 + c);
                float2 v11 = *(const float2*)(sr8 + c + 8);
                float2 s0 = *(const float2*)(sl + c);
                float2 s1 = *(const float2*)(sl + c + 8);
                uint2 p0 = split2h(v00.x * s0.x, v00.y * s0.y);
                uint2 p1 = split2h(v10.x * s0.x, v10.y * s0.y);
                uint2 p2 = split2h(v01.x * s1.x, v01.y * s1.y);
                uint2 p3 = split2h(v11.x * s1.x, v11.y * s1.y);
                ah[f][t][0] = p0.x; al[f][t][0] = p0.y;
                ah[f][t][1] = p1.x; al[f][t][1] = p1.y;
                ah[f][t][2] = p2.x; al[f][t][2] = p2.y;
                ah[f][t][3] = p3.x; al[f][t][3] = p3.y;
            }
        }

        // ---- persistent output accumulators (o = 64) ----
        float D2[2][8][4];
#pragma unroll
        for (int f = 0; f < 2; f++)
#pragma unroll
            for (int q = 0; q < 8; q++)
#pragma unroll
                for (int e = 0; e < 4; e++) D2[f][q][e] = 0.0f;

#pragma unroll
        for (int jh = 0; jh < 2; jh++) {
            // ---- GEMM1: D1[32 m][64 j-half], 2-term fp16 ----
            float D1[2][8][4];
#pragma unroll
            for (int f = 0; f < 2; f++)
#pragma unroll
                for (int q = 0; q < 8; q++)
#pragma unroll
                    for (int e = 0; e < 4; e++) D1[f][q][e] = 0.0f;

#pragma unroll
            for (int t = 0; t < 4; t++) {
#pragma unroll
                for (int qq = 0; qq < 4; qq++) {
                    uint32_t bh[4];
                    ldsm4(bh, preB1 + jh * 9216 + qq * 2304 + t * 32);
                    mma16816(D1[0][2 * qq],     ah[0][t], bh[0], bh[1]);
                    mma16816(D1[0][2 * qq + 1], ah[0][t], bh[2], bh[3]);
                    mma16816(D1[1][2 * qq],     ah[1][t], bh[0], bh[1]);
                    mma16816(D1[1][2 * qq + 1], ah[1][t], bh[2], bh[3]);
                    mma16816(D1[0][2 * qq],     al[0][t], bh[0], bh[1]);
                    mma16816(D1[0][2 * qq + 1], al[0][t], bh[2], bh[3]);
                    mma16816(D1[1][2 * qq],     al[1][t], bh[0], bh[1]);
                    mma16816(D1[1][2 * qq + 1], al[1][t], bh[2], bh[3]);
                }
            }

            // ---- relu(H + P[dist]) in registers ----
#pragma unroll
            for (int f = 0; f < 2; f++) {
                const int m_t = mw + 16 * f + lr;
                const float* P0 = g_P + (size_t)(n - m_t + 512) * HID + jh * 64;
                const float* P1 = P0 - 8 * HID;   // row m_t+8
#pragma unroll
                for (int q = 0; q < 8; q++) {
                    const int jc = 8 * q + fc0;
                    float2 p0 = __ldg((const float2*)(P0 + jc));
                    float2 p1 = __ldg((const float2*)(P1 + jc));
                    D1[f][q][0] = fmaxf(D1[f][q][0] + p0.x, 0.0f);
                    D1[f][q][1] = fmaxf(D1[f][q][1] + p0.y, 0.0f);
                    D1[f][q][2] = fmaxf(D1[f][q][2] + p1.x, 0.0f);
                    D1[f][q][3] = fmaxf(D1[f][q][3] + p1.y, 0.0f);
                }
            }

            // ---- GEMM2 K-partial: D2 += Hrelu(j-half) @ W2(j-half) ----
#pragma unroll
            for (int t2 = 0; t2 < 4; t2++) {
                uint32_t ah2[2][4], al2[2][4];
#pragma unroll
                for (int f = 0; f < 2; f++) {
                    uint2 s0 = split2h(D1[f][2 * t2][0],     D1[f][2 * t2][1]);
                    uint2 s1 = split2h(D1[f][2 * t2][2],     D1[f][2 * t2][3]);
                    uint2 s2 = split2h(D1[f][2 * t2 + 1][0], D1[f][2 * t2 + 1][1]);
                    uint2 s3 = split2h(D1[f][2 * t2 + 1][2], D1[f][2 * t2 + 1][3]);
                    ah2[f][0] = s0.x; al2[f][0] = s0.y;
                    ah2[f][1] = s1.x; al2[f][1] = s1.y;
                    ah2[f][2] = s2.x; al2[f][2] = s2.y;
                    ah2[f][3] = s3.x; al2[f][3] = s3.y;
                }
#pragma unroll
                for (int qq = 0; qq < 4; qq++) {
                    uint32_t bh[4];
                    ldsm4(bh, preB2 + jh * 128 + qq * 4352 + t2 * 32);
                    mma16816(D2[0][2 * qq],     ah2[0], bh[0], bh[1]);
                    mma16816(D2[0][2 * qq + 1], ah2[0], bh[2], bh[3]);
                    mma16816(D2[1][2 * qq],     ah2[1], bh[0], bh[1]);
                    mma16816(D2[1][2 * qq + 1], ah2[1], bh[2], bh[3]);
                    mma16816(D2[0][2 * qq],     al2[0], bh[0], bh[1]);
                    mma16816(D2[0][2 * qq + 1], al2[0], bh[2], bh[3]);
                    mma16816(D2[1][2 * qq],     al2[1], bh[0], bh[1]);
                    mma16816(D2[1][2 * qq + 1], al2[1], bh[2], bh[3]);
                }
            }
        }

        // ---- epilogue: + b2 (from smem), store fp32 ----
#pragma unroll
        for (int f = 0; f < 2; f++) {
            const int m_t = mw + 16 * f + lr;
            float* ob = out + (((size_t)b * N_ + n) * N_ + m_t) * EMB;
#pragma unroll
            for (int q = 0; q < 8; q++) {
                const int oc = 8 * q + fc0;
                float2 bb = *(const float2*)(b2s + oc);
                *(float2*)(ob + oc) =
                    make_float2(D2[f][q][0] + bb.x, D2[f][q][1] + bb.y);
                *(float2*)(ob + 8 * EMB + oc) =
                    make_float2(D2[f][q][2] + bb.x, D2[f][q][3] + bb.y);
            }
        }
    }
}

// ---------------- launch ----------------
extern "C" void kernel_launch(void* const* d_in, const int* in_sizes, int n_in,
                              void* d_out, int out_size) {
    const float* s       = (const float*)d_in[0];
    const float* W_left  = (const float*)d_in[1];
    const float* b_left  = (const float*)d_in[2];
    const float* W_right = (const float*)d_in[3];
    const float* b_right = (const float*)d_in[4];
    const float* emb     = (const float*)d_in[5];
    const float* W1      = (const float*)d_in[6];
    const float* b1      = (const float*)d_in[7];
    const float* W2      = (const float*)d_in[8];
    const float* b2      = (const float*)d_in[9];
    float* out = (float*)d_out;

    cudaFuncSetAttribute(proj2_kernel,
                         cudaFuncAttributeMaxDynamicSharedMemorySize, 73728);
    cudaFuncSetAttribute(pair_mma_kernel,
                         cudaFuncAttributeMaxDynamicSharedMemorySize, SMEM_MAIN);

    proj2_kernel<<<64, 256, 73728>>>(s, W_left, b_left, W_right, b_right);
    prep_kernel<<<32, 256>>>(W1, W2);
    pos_kernel<<<NPOS, 128>>>(emb, W1, b1);
    pair_mma_kernel<<<dim3(N_, B_), 256, SMEM_MAIN>>>(b2, out);
}

// round 12
// speedup vs baseline: 1.0528x; 1.0528x over previous
#include <cuda_runtime.h>
#include <cuda_fp16.h>
#include <stdint.h>

#define B_ 2
#define N_ 512
#define IN_DIM 512
#define EMB 64
#define HID 128
#define NPOS 1025

// ---------------- device scratch (no cudaMalloc allowed) ----------------
__device__ float g_sl[B_ * N_ * EMB];
__device__ float g_sr[B_ * N_ * EMB];
__device__ float g_P[NPOS * HID];
__device__ float g_W1Tf[HID * EMB];            // fp32 W1_top^T [j][d]
__device__ unsigned short g_W2Th[EMB * HID];   // fp16(W2^T) [o][j]
// SR pre-split into mma fragment layout: [b][mb(32)][lane(32)][16 words]
__device__ uint32_t g_srfh[B_ * 32 * 32 * 16];
__device__ uint32_t g_srfl[B_ * 32 * 32 * 16];

// ---------------- helpers ----------------
__device__ __forceinline__ uint32_t smem_u32_of(const void* p) {
    uint32_t a;
    asm("{ .reg .u64 t; cvta.to.shared.u64 t, %1; cvt.u32.u64 %0, t; }"
        : "=r"(a) : "l"(p));
    return a;
}
// fp16 hi/lo split of a float pair -> (hi_half2, lo_half2)
__device__ __forceinline__ uint2 split2h(float e0, float e1) {
    __half2 h = __floats2half2_rn(e0, e1);
    float f0 = __half2float(__low2half(h));
    float f1 = __half2float(__high2half(h));
    __half2 lo = __floats2half2_rn(e0 - f0, e1 - f1);
    return make_uint2(*reinterpret_cast<uint32_t*>(&h),
                      *reinterpret_cast<uint32_t*>(&lo));
}
__device__ __forceinline__ void mma16816(float* c, const uint32_t* a,
                                         uint32_t b0, uint32_t b1) {
    asm volatile(
        "mma.sync.aligned.m16n8k16.row.col.f32.f16.f16.f32 "
        "{%0,%1,%2,%3}, {%4,%5,%6,%7}, {%8,%9}, {%0,%1,%2,%3};"
        : "+f"(c[0]), "+f"(c[1]), "+f"(c[2]), "+f"(c[3])
        : "r"(a[0]), "r"(a[1]), "r"(a[2]), "r"(a[3]), "r"(b0), "r"(b1));
}
__device__ __forceinline__ void ldsm4(uint32_t* r, uint32_t addr) {
    asm volatile("ldmatrix.sync.aligned.m8n8.x4.shared.b16 {%0,%1,%2,%3}, [%4];"
                 : "=r"(r[0]), "=r"(r[1]), "=r"(r[2]), "=r"(r[3]) : "r"(addr));
}

// ---------------- kernel 1: projections ----------------
__global__ void proj2_kernel(const float* __restrict__ s,
                             const float* __restrict__ Wl, const float* __restrict__ bl,
                             const float* __restrict__ Wr, const float* __restrict__ br) {
    extern __shared__ float psm[];
    float* SsT = psm;              // [512][20]
    float* Wc  = psm + 512 * 20;   // [64][128]

    const int t = threadIdx.x;
    const int r0 = blockIdx.x * 16;

    for (int i = t; i < 16 * IN_DIM; i += 256) {
        int row = i >> 9, k = i & 511;
        SsT[k * 20 + row] = s[(size_t)(r0 + row) * IN_DIM + k];
    }

    const int col = t & 127, rg = t >> 7;
    float acc[8];
    const float bias = (col < 64) ? bl[col] : br[col - 64];
#pragma unroll
    for (int r = 0; r < 8; r++) acc[r] = bias;
    __syncthreads();

    for (int kt = 0; kt < 8; kt++) {
        for (int i = t; i < 64 * 128; i += 256) {
            int k = i >> 7, c = i & 127;
            Wc[i] = (c < 64) ? Wl[(size_t)(kt * 64 + k) * 64 + c]
                             : Wr[(size_t)(kt * 64 + k) * 64 + (c - 64)];
        }
        __syncthreads();
#pragma unroll 4
        for (int k = 0; k < 64; k++) {
            float w = Wc[k * 128 + col];
            const float* sp = &SsT[(kt * 64 + k) * 20 + rg * 8];
            float4 a0 = *(const float4*)sp;
            float4 a1 = *(const float4*)(sp + 4);
            acc[0] += a0.x * w; acc[1] += a0.y * w; acc[2] += a0.z * w; acc[3] += a0.w * w;
            acc[4] += a1.x * w; acc[5] += a1.y * w; acc[6] += a1.z * w; acc[7] += a1.w * w;
        }
        __syncthreads();
    }
#pragma unroll
    for (int r = 0; r < 8; r++) {
        int row = r0 + rg * 8 + r;
        if (col < 64) g_sl[(size_t)row * 64 + col] = acc[r];
        else          g_sr[(size_t)row * 64 + (col - 64)] = acc[r];
    }
}

// ---------------- kernel 2: weight transposes ----------------
__global__ void prep_kernel(const float* __restrict__ W1, const float* __restrict__ W2) {
    int i = blockIdx.x * 256 + threadIdx.x;
    if (i < HID * EMB) {
        {
            int j = i >> 6, d = i & 63;
            g_W1Tf[i] = W1[d * HID + j];
        }
        {
            int o = i & 63, jj = i >> 6;
            g_W2Th[o * HID + jj] = __half_as_ushort(__float2half_rn(W2[jj * EMB + o]));
        }
    }
}

// ---------------- kernel 2b: SR -> fragment-layout fp16 hi/lo ----------------
// idx -> (b, mb, lane, r) ; r = t*4+e ; frag elem e: row += (e&1)*8, col += (e&2)*4
__global__ void prep_srf_kernel() {
    int idx = blockIdx.x * 256 + threadIdx.x;   // 32768 total
    int r = idx & 15, l = (idx >> 4) & 31, mb = (idx >> 9) & 31, b = idx >> 14;
    int t = r >> 2, e = r & 3;
    int row = mb * 16 + (l >> 2) + (e & 1) * 8;
    int c = (l & 3) * 2 + 16 * t + (e & 2) * 4;
    const float* p = g_sr + ((size_t)b * N_ + row) * EMB + c;
    uint2 s = split2h(p[0], p[1]);
    g_srfh[idx] = s.x;
    g_srfl[idx] = s.y;
}

// ---------------- kernel 3: positional table ----------------
__global__ void pos_kernel(const float* __restrict__ emb,
                           const float* __restrict__ W1,
                           const float* __restrict__ b1) {
    __shared__ float erow[EMB];
    const int dist = blockIdx.x;
    const int h = threadIdx.x;
    if (h < EMB) erow[h] = emb[dist * EMB + h];
    __syncthreads();
    float acc = b1[h];
#pragma unroll
    for (int d = 0; d < EMB; d++)
        acc = fmaf(erow[d], W1[(EMB + d) * HID + h], acc);
    g_P[dist * HID + h] = acc;
}

// ---------------- main kernel: folded-B1, coalesced A-frag LDG, 2 CTAs ----------------
// smem: sl 256B | b2 256B | W1' [128 j][72 fp16] 144B-stride | W2 [64 o][136] 272B-stride
#define OFF_SL   0
#define OFF_B2S  256
#define OFF_W1   512
#define OFF_W2   (OFF_W1 + 18432)
#define SMEM_MAIN (OFF_W2 + 17408)   // 36352 bytes

__global__ __launch_bounds__(256, 2)
void pair_mma_kernel(const float* __restrict__ b2, float* __restrict__ out) {
    extern __shared__ char sm[];
    const uint32_t smb = smem_u32_of(sm);
    const int tid = threadIdx.x;
    const int w = tid >> 5, l = tid & 31;
    const int n = blockIdx.x, b = blockIdx.y;

    float* sl = (float*)(sm + OFF_SL);
    float* b2s = (float*)(sm + OFF_B2S);
    if (tid < 64) {
        sl[tid] = g_sl[((size_t)b * N_ + n) * EMB + tid];
        b2s[tid] = b2[tid];
    }
    for (int i = tid; i < 2048; i += 256) {
        int o = i >> 5, j8 = (i & 31) * 8;
        *(uint2*)(sm + OFF_W2 + o * 272 + j8) = ((const uint2*)g_W2Th)[i];
    }
    __syncthreads();   // sl ready for the fold below

    // build B1'[j][d] = fp16(W1^T[j][d] * sl[d]) into smem (ldsm layout)
    for (int g = tid; g < 2048; g += 256) {
        int j = g >> 4, d0 = (g & 15) * 4;
        float4 wv = *(const float4*)(g_W1Tf + j * 64 + d0);
        float4 sv = *(const float4*)(sl + d0);
        __half2 h0 = __floats2half2_rn(wv.x * sv.x, wv.y * sv.y);
        __half2 h1 = __floats2half2_rn(wv.z * sv.z, wv.w * sv.w);
        *(uint2*)(sm + OFF_W1 + j * 144 + d0 * 2) =
            make_uint2(*reinterpret_cast<uint32_t*>(&h0),
                       *reinterpret_cast<uint32_t*>(&h1));
    }
    __syncthreads();   // smem read-only below: mt loop has NO barriers

    // ---- per-thread ldmatrix base addresses for B operands (x4 forms) ----
    const uint32_t preB1 = smb + OFF_W1 +
        ((l & 7) + ((l >> 4) << 3)) * 144 + ((l >> 3) & 1) * 16;
    const uint32_t preB2 = smb + OFF_W2 +
        ((l & 7) + ((l >> 4) << 3)) * 272 + ((l >> 3) & 1) * 16;

    const int fc0 = (l & 3) * 2;
    const int fr0 = 16 * w + (l >> 2);

    for (int mt = 0; mt < 4; mt++) {
        const int m_t = mt * 128 + fr0;
        const int mb = mt * 8 + w;

        // ---- A fragments: pure coalesced LDG.128 (pre-split in prep_srf) ----
        uint4 hv[4], lv[4];
        {
            const uint4* hp = (const uint4*)(g_srfh +
                ((((size_t)b * 32 + mb) * 32 + l) * 16));
            const uint4* lp = (const uint4*)(g_srfl +
                ((((size_t)b * 32 + mb) * 32 + l) * 16));
#pragma unroll
            for (int t = 0; t < 4; t++) { hv[t] = hp[t]; lv[t] = lp[t]; }
        }

        // ---- GEMM1: H[16,128] per warp = SR @ B1'^T, 2-term fp16 ----
        float D1[16][4];
#pragma unroll
        for (int q = 0; q < 16; q++)
#pragma unroll
            for (int e = 0; e < 4; e++) D1[q][e] = 0.0f;

#pragma unroll
        for (int t = 0; t < 4; t++) {
#pragma unroll
            for (int qq = 0; qq < 8; qq++) {
                uint32_t bh[4];
                ldsm4(bh, preB1 + qq * 2304 + t * 32);
                mma16816(D1[2 * qq],     (const uint32_t*)&hv[t], bh[0], bh[1]);
                mma16816(D1[2 * qq + 1], (const uint32_t*)&hv[t], bh[2], bh[3]);
                mma16816(D1[2 * qq],     (const uint32_t*)&lv[t], bh[0], bh[1]);
                mma16816(D1[2 * qq + 1], (const uint32_t*)&lv[t], bh[2], bh[3]);
            }
        }

        // ---- relu(H + P[dist]) in registers ----
        {
            const float* P0 = g_P + (size_t)(n - m_t + 512) * HID;
            const float* P1 = P0 - 8 * HID;   // row m_t+8
#pragma unroll
            for (int q = 0; q < 16; q++) {
                const int jc = 8 * q + fc0;
                float2 p0 = __ldg((const float2*)(P0 + jc));
                float2 p1 = __ldg((const float2*)(P1 + jc));
                D1[q][0] = fmaxf(D1[q][0] + p0.x, 0.0f);
                D1[q][1] = fmaxf(D1[q][1] + p0.y, 0.0f);
                D1[q][2] = fmaxf(D1[q][2] + p1.x, 0.0f);
                D1[q][3] = fmaxf(D1[q][3] + p1.y, 0.0f);
            }
        }

        // ---- GEMM2: out = Hrelu @ W2, 2-term fp16 (A from registers) ----
        float D2[8][4];
#pragma unroll
        for (int q = 0; q < 8; q++)
#pragma unroll
            for (int e = 0; e < 4; e++) D2[q][e] = 0.0f;

#pragma unroll
        for (int t2 = 0; t2 < 8; t2++) {
            uint32_t ah2[4], al2[4];
            {
                uint2 s0 = split2h(D1[2 * t2][0],     D1[2 * t2][1]);
                uint2 s1 = split2h(D1[2 * t2][2],     D1[2 * t2][3]);
                uint2 s2 = split2h(D1[2 * t2 + 1][0], D1[2 * t2 + 1][1]);
                uint2 s3 = split2h(D1[2 * t2 + 1][2], D1[2 * t2 + 1][3]);
                ah2[0] = s0.x; al2[0] = s0.y;
                ah2[1] = s1.x; al2[1] = s1.y;
                ah2[2] = s2.x; al2[2] = s2.y;
                ah2[3] = s3.x; al2[3] = s3.y;
            }
#pragma unroll
            for (int qq = 0; qq < 4; qq++) {
                uint32_t bh[4];
                ldsm4(bh, preB2 + qq * 4352 + t2 * 32);
                mma16816(D2[2 * qq],     ah2, bh[0], bh[1]);
                mma16816(D2[2 * qq + 1], ah2, bh[2], bh[3]);
                mma16816(D2[2 * qq],     al2, bh[0], bh[1]);
                mma16816(D2[2 * qq + 1], al2, bh[2], bh[3]);
            }
        }

        // ---- epilogue: + b2 (from smem), store fp32 ----
        {
            float* ob = out + (((size_t)b * N_ + n) * N_ + m_t) * EMB;
#pragma unroll
            for (int q = 0; q < 8; q++) {
                const int oc = 8 * q + fc0;
                float2 bb = *(const float2*)(b2s + oc);
                *(float2*)(ob + oc) =
                    make_float2(D2[q][0] + bb.x, D2[q][1] + bb.y);
                *(float2*)(ob + 8 * EMB + oc) =
                    make_float2(D2[q][2] + bb.x, D2[q][3] + bb.y);
            }
        }
    }
}

// ---------------- launch ----------------
extern "C" void kernel_launch(void* const* d_in, const int* in_sizes, int n_in,
                              void* d_out, int out_size) {
    const float* s       = (const float*)d_in[0];
    const float* W_left  = (const float*)d_in[1];
    const float* b_left  = (const float*)d_in[2];
    const float* W_right = (const float*)d_in[3];
    const float* b_right = (const float*)d_in[4];
    const float* emb     = (const float*)d_in[5];
    const float* W1      = (const float*)d_in[6];
    const float* b1      = (const float*)d_in[7];
    const float* W2      = (const float*)d_in[8];
    const float* b2      = (const float*)d_in[9];
    float* out = (float*)d_out;

    cudaFuncSetAttribute(proj2_kernel,
                         cudaFuncAttributeMaxDynamicSharedMemorySize, 73728);
    cudaFuncSetAttribute(pair_mma_kernel,
                         cudaFuncAttributeMaxDynamicSharedMemorySize, SMEM_MAIN);

    proj2_kernel<<<64, 256, 73728>>>(s, W_left, b_left, W_right, b_right);
    prep_kernel<<<32, 256>>>(W1, W2);
    prep_srf_kernel<<<128, 256>>>();
    pos_kernel<<<NPOS, 128>>>(emb, W1, b1);
    pair_mma_kernel<<<dim3(N_, B_), 256, SMEM_MAIN>>>(b2, out);
}